// round 2
// baseline (speedup 1.0000x reference)
#include <cuda_runtime.h>
#include <cstdint>

// ============================================================================
// CAM module via Gram-matrix restructuring.
//   X_aug[b] : 193 x 65536   (192 input channels + constant-1 row, padded to 200)
//   G[b]     = X_aug X_aug^T                       (kernel 1, fp32, f32x2 FMA)
//   T[b]     = Wk_aug G                            (kernel 2a)
//   E[b]     = Wq_aug T^T * C^-0.5 ; A = softmax   (kernel 2b)
//   M[b]     = A Wv_aug                            (kernel 2b)
//   out[b]   = M X_aug                             (kernel 3, fp32, f32x2 FMA)
// ============================================================================

#define NPIX   65536
#define JP     200        // padded augmented channel dim (192 ch + 1s row + pad)
#define XSTR   204        // smem row stride (floats) for gram kernel
#define GRAM_TN 32        // pixels per smem tile (gram)
#define K3_TN  256        // pixels per CTA tile (out kernel)
#define K3_JC  32         // j-chunk (out kernel)
#define XS3    264        // smem X stride (out kernel)
#define MSTR   68         // smem M stride (out kernel)

__device__ float g_G[4 * JP * JP];    // Gram matrices
__device__ float g_T[4 * 64 * JP];    // T[b][d][i]
__device__ float g_M[4 * 64 * JP];    // M_aug[b][c][j]

// ---- packed f32x2 helpers --------------------------------------------------
static __device__ __forceinline__ unsigned long long pack2(float x) {
    unsigned long long r;
    asm("mov.b64 %0, {%1, %1};" : "=l"(r) : "f"(x));
    return r;
}
static __device__ __forceinline__ void ffma2(unsigned long long& d,
                                             unsigned long long a,
                                             unsigned long long b) {
    asm("fma.rn.f32x2 %0, %1, %2, %0;" : "+l"(d) : "l"(a), "l"(b));
}
static __device__ __forceinline__ float2 unpack2(unsigned long long v) {
    float2 f;
    asm("mov.b64 {%0, %1}, %2;" : "=f"(f.x), "=f"(f.y) : "l"(v));
    return f;
}

// ---- kernel 0: zero the Gram accumulators ----------------------------------
__global__ void cam_zeroG() {
    int g = blockIdx.x * blockDim.x + threadIdx.x;
    if (g < 4 * JP * JP) g_G[g] = 0.0f;
}

// ---- kernel 1: per-batch Gram matrix G = X_aug X_aug^T ---------------------
// Upper-triangle 8x8 thread blocks over a 25x25 block grid (325 active threads
// of 384). Each CTA streams pixel tiles and accumulates in registers, then
// atomicAdds into g_G (mirroring off-diagonal blocks).
__global__ __launch_bounds__(384, 1)
void cam_gram(const float* __restrict__ rgb,
              const float* __restrict__ hsv,
              const float* __restrict__ lab) {
    __shared__ __align__(16) float Xs[GRAM_TN * XSTR];

    const int b = blockIdx.y;
    const int t = threadIdx.x;
    const bool active = (t < 325);

    // enumerate upper-triangle block (ti, tj), ti <= tj, over 25x25 blocks
    int ti = 0, tj = 0;
    {
        int rem = active ? t : 0;
        int r = 0;
        while (rem >= 25 - r) { rem -= 25 - r; r++; }
        ti = r; tj = r + rem;
    }

    const float* bases[3] = {
        rgb + (size_t)b * 64 * NPIX,
        hsv + (size_t)b * 64 * NPIX,
        lab + (size_t)b * 64 * NPIX
    };

    unsigned long long acc[8][4];
#pragma unroll
    for (int r = 0; r < 8; r++)
#pragma unroll
        for (int q = 0; q < 4; q++) acc[r][q] = 0ull;

    const int ntiles = NPIX / GRAM_TN;  // 2048
    for (int tile = blockIdx.x; tile < ntiles; tile += gridDim.x) {
        const int n0 = tile * GRAM_TN;
        // load [JP x 32] tile, transposed into Xs[p][j]
        for (int idx = t; idx < JP * GRAM_TN; idx += 384) {
            const int j = idx >> 5;
            const int p = idx & 31;
            float v;
            if (j < 192) {
                v = bases[j >> 6][(size_t)(j & 63) * NPIX + n0 + p];
            } else {
                v = (j == 192) ? 1.0f : 0.0f;
            }
            Xs[p * XSTR + j] = v;
        }
        __syncthreads();

#pragma unroll 1
        for (int p = 0; p < GRAM_TN; p++) {
            const float* row = Xs + p * XSTR;
            const float4 a0 = *(const float4*)(row + ti * 8);
            const float4 a1 = *(const float4*)(row + ti * 8 + 4);
            const ulonglong2 b01 = *(const ulonglong2*)(row + tj * 8);
            const ulonglong2 b23 = *(const ulonglong2*)(row + tj * 8 + 4);
            const unsigned long long bb[4] = {b01.x, b01.y, b23.x, b23.y};
            const float av[8] = {a0.x, a0.y, a0.z, a0.w, a1.x, a1.y, a1.z, a1.w};
#pragma unroll
            for (int r = 0; r < 8; r++) {
                const unsigned long long as = pack2(av[r]);
#pragma unroll
                for (int q = 0; q < 4; q++) ffma2(acc[r][q], as, bb[q]);
            }
        }
        __syncthreads();
    }

    if (active) {
        float* Gb = g_G + b * JP * JP;
#pragma unroll
        for (int r = 0; r < 8; r++) {
            const int row = ti * 8 + r;
#pragma unroll
            for (int q = 0; q < 4; q++) {
                const float2 v = unpack2(acc[r][q]);
                const int c0 = tj * 8 + 2 * q;
                atomicAdd(&Gb[row * JP + c0], v.x);
                atomicAdd(&Gb[row * JP + c0 + 1], v.y);
                if (ti != tj) {
                    atomicAdd(&Gb[c0 * JP + row], v.x);
                    atomicAdd(&Gb[(c0 + 1) * JP + row], v.y);
                }
            }
        }
    }
}

// ---- kernel 2a: T[b][d][i] = sum_j Wk_aug[d,j] G[b][j][i] ------------------
__global__ void cam_projk(const float* __restrict__ Wk,
                          const float* __restrict__ bk) {
    const int g = blockIdx.x * blockDim.x + threadIdx.x;
    if (g >= 4 * 64 * JP) return;
    const int i = g % JP;
    const int d = (g / JP) % 64;
    const int b = g / (JP * 64);
    const float* Gb = g_G + b * JP * JP;
    float acc = 0.0f;
#pragma unroll 4
    for (int j = 0; j < 192; j++) acc += Wk[d * 192 + j] * Gb[j * JP + i];
    acc += bk[d] * Gb[192 * JP + i];
    g_T[g] = acc;  // g == ((b*64)+d)*JP + i
}

// ---- kernel 2b: energy -> softmax -> M = A Wv_aug --------------------------
// One block per (b, c): 64 threads, thread d owns energy[c][d].
__global__ void cam_attn(const float* __restrict__ Wq,
                         const float* __restrict__ bq,
                         const float* __restrict__ Wv,
                         const float* __restrict__ bv) {
    __shared__ float se[64];
    __shared__ float sa[64];
    const int c = blockIdx.x;
    const int b = blockIdx.y;
    const int d = threadIdx.x;

    const float* Tb = g_T + (b * 64 + d) * JP;
    float e = 0.0f;
#pragma unroll 4
    for (int i = 0; i < 192; i++) e += Wq[c * 192 + i] * Tb[i];
    e += bq[c] * Tb[192];
    e *= 0.125f;  // C^-0.5, C=64
    se[d] = e;
    __syncthreads();

    float mx = -1e30f;
    for (int k = 0; k < 64; k++) mx = fmaxf(mx, se[k]);
    float s = 0.0f;
    for (int k = 0; k < 64; k++) s += expf(se[k] - mx);
    sa[d] = expf(e - mx) / s;
    __syncthreads();

    float* Mrow = g_M + (b * 64 + c) * JP;
    for (int j = d; j < 193; j += 64) {
        float m = 0.0f;
        if (j < 192) {
            for (int dd = 0; dd < 64; dd++) m += sa[dd] * Wv[dd * 192 + j];
        } else {
            for (int dd = 0; dd < 64; dd++) m += sa[dd] * bv[dd];
        }
        Mrow[j] = m;
    }
}

// ---- kernel 3: out[b] = M[b] X_aug[b] --------------------------------------
// CTA tile: 64 channels x 256 pixels; thread tile 8x8; j-chunked smem staging.
__global__ __launch_bounds__(256, 1)
void cam_out(const float* __restrict__ rgb,
             const float* __restrict__ hsv,
             const float* __restrict__ lab,
             float* __restrict__ out) {
    __shared__ __align__(16) float Ms[K3_JC * MSTR];
    __shared__ __align__(16) float Xs[K3_JC * XS3];

    const int b = blockIdx.y;
    const int gn0 = blockIdx.x * K3_TN;
    const int t = threadIdx.x;
    const int n0 = (t & 31) * 8;
    const int c0 = (t >> 5) * 8;

    const float* Mb = g_M + b * 64 * JP;
    const float* bases[3] = {
        rgb + (size_t)b * 64 * NPIX,
        hsv + (size_t)b * 64 * NPIX,
        lab + (size_t)b * 64 * NPIX
    };

    unsigned long long acc[8][4];
#pragma unroll
    for (int r = 0; r < 8; r++) {
        const float cv = Mb[(c0 + r) * JP + 192];  // constant (bias) column
#pragma unroll
        for (int q = 0; q < 4; q++) acc[r][q] = pack2(cv);
    }

    for (int jc = 0; jc < 192; jc += K3_JC) {
        // stage M chunk: Ms[jl][c] = Mb[c][jc+jl]
        for (int idx = t; idx < K3_JC * 64; idx += 256) {
            const int c = idx / K3_JC;
            const int jl = idx % K3_JC;
            Ms[jl * MSTR + c] = Mb[c * JP + jc + jl];
        }
        // stage X chunk: Xs[jl][n]
        for (int idx = t; idx < K3_JC * K3_TN; idx += 256) {
            const int jl = idx >> 8;
            const int n = idx & 255;
            const int j = jc + jl;
            Xs[jl * XS3 + n] = bases[j >> 6][(size_t)(j & 63) * NPIX + gn0 + n];
        }
        __syncthreads();

#pragma unroll 1
        for (int jl = 0; jl < K3_JC; jl++) {
            const float4 a0 = *(const float4*)(Ms + jl * MSTR + c0);
            const float4 a1 = *(const float4*)(Ms + jl * MSTR + c0 + 4);
            const ulonglong2 b01 = *(const ulonglong2*)(Xs + jl * XS3 + n0);
            const ulonglong2 b23 = *(const ulonglong2*)(Xs + jl * XS3 + n0 + 4);
            const unsigned long long bb[4] = {b01.x, b01.y, b23.x, b23.y};
            const float av[8] = {a0.x, a0.y, a0.z, a0.w, a1.x, a1.y, a1.z, a1.w};
#pragma unroll
            for (int r = 0; r < 8; r++) {
                const unsigned long long as = pack2(av[r]);
#pragma unroll
                for (int q = 0; q < 4; q++) ffma2(acc[r][q], as, bb[q]);
            }
        }
        __syncthreads();
    }

#pragma unroll
    for (int r = 0; r < 8; r++) {
        const float2 u0 = unpack2(acc[r][0]);
        const float2 u1 = unpack2(acc[r][1]);
        const float2 u2 = unpack2(acc[r][2]);
        const float2 u3 = unpack2(acc[r][3]);
        float* op = out + (size_t)(b * 64 + c0 + r) * NPIX + gn0 + n0;
        float4 o0 = make_float4(u0.x, u0.y, u1.x, u1.y);
        float4 o1 = make_float4(u2.x, u2.y, u3.x, u3.y);
        *(float4*)op = o0;
        *(float4*)(op + 4) = o1;
    }
}

// ---- launch ----------------------------------------------------------------
extern "C" void kernel_launch(void* const* d_in, const int* in_sizes, int n_in,
                              void* d_out, int out_size) {
    const float* rgb = (const float*)d_in[0];
    const float* hsv = (const float*)d_in[1];
    const float* lab = (const float*)d_in[2];
    const float* Wq  = (const float*)d_in[3];
    const float* bq  = (const float*)d_in[4];
    const float* Wk  = (const float*)d_in[5];
    const float* bk  = (const float*)d_in[6];
    const float* Wv  = (const float*)d_in[7];
    const float* bv  = (const float*)d_in[8];
    float* out = (float*)d_out;

    cam_zeroG<<<(4 * JP * JP + 255) / 256, 256>>>();
    cam_gram<<<dim3(37, 4), 384>>>(rgb, hsv, lab);
    cam_projk<<<(4 * 64 * JP + 255) / 256, 256>>>(Wk, bk);
    cam_attn<<<dim3(64, 4), 64>>>(Wq, bq, Wv, bv);
    cam_out<<<dim3(NPIX / K3_TN, 4), 256>>>(rgb, hsv, lab, out);
}

// round 5
// speedup vs baseline: 1.1368x; 1.1368x over previous
#include <cuda_runtime.h>
#include <cuda_bf16.h>
#include <cstdint>

// ============================================================================
// CAM module via Gram restructuring, tensor path = mma.sync bf16 (sm_100-safe).
//   X_aug[b] : 208 x 65536  (192 ch + ones row + 15 zero rows)
//   Gp       = split-K partial grams, bf16 hi/lo 3-combo mma.sync (upper tri)
//   G        = reduce + mirror
//   T2[b][i][d] = sum_j G[i][j] Wk_aug[d][j]
//   E = Wq_aug T2 * 0.125 ; A = softmax ; M = A Wv_aug  (stored bf16 hi/lo)
//   out[b]   = M X_aug  via mma.sync (ldmatrix.trans for X)
// ============================================================================

#define NPIX   65536
#define JT     208
#define SPLITS 37
#define GSTR   72     // gram smem row stride in bf16 (conflict-free: 4-bank shift)
#define ASTR   216    // out-kernel A smem stride (bf16)
#define XSTR3  264    // out-kernel X smem stride (bf16)

__device__ float g_Gp[4 * SPLITS * JT * JT];   // 25.6 MB split-K scratch
__device__ float g_G[4 * JT * JT];
__device__ float g_T2[4 * 193 * 64];
__device__ unsigned short g_Mhi[4 * 64 * JT];
__device__ unsigned short g_Mlo[4 * 64 * JT];

// ---------------------------------------------------------------------------
static __device__ __forceinline__ uint32_t smem_u32(const void* p) {
    uint32_t a;
    asm("{ .reg .u64 t; cvta.to.shared.u64 t, %1; cvt.u32.u64 %0, t; }"
        : "=r"(a) : "l"(p));
    return a;
}

#define MMA16816(d, a0, a1, a2, a3, b0, b1) \
    asm volatile("mma.sync.aligned.m16n8k16.row.col.f32.bf16.bf16.f32 " \
        "{%0,%1,%2,%3}, {%4,%5,%6,%7}, {%8,%9}, {%0,%1,%2,%3};" \
        : "+f"((d)[0]), "+f"((d)[1]), "+f"((d)[2]), "+f"((d)[3]) \
        : "r"(a0), "r"(a1), "r"(a2), "r"(a3), "r"(b0), "r"(b1))

#define LDSM_X2_T(r0, r1, addr) \
    asm volatile("ldmatrix.sync.aligned.m8n8.x2.trans.shared.b16 {%0,%1}, [%2];" \
        : "=r"(r0), "=r"(r1) : "r"(addr))

static __device__ __forceinline__ void split_bf16(float x, unsigned short& h,
                                                  unsigned short& lo) {
    __nv_bfloat16 hb = __float2bfloat16(x);
    __nv_bfloat16 lb = __float2bfloat16(x - __bfloat162float(hb));
    h = __bfloat16_as_ushort(hb);
    lo = __bfloat16_as_ushort(lb);
}

// ---------------------------------------------------------------------------
// kernel 1: split-K Gram, upper-triangle tiles, bf16 hi/lo mma.sync
// grid (37, 4), 256 threads, dyn smem 2 planes x [208][72] bf16
// ---------------------------------------------------------------------------
#define GRAM_SMEM (2 * JT * GSTR * 2)

__global__ __launch_bounds__(256, 1)
void cam_gram_mma(const float* __restrict__ rgb,
                  const float* __restrict__ hsv,
                  const float* __restrict__ lab) {
    extern __shared__ __align__(16) __nv_bfloat16 gsm[];
    __nv_bfloat16* hiP = gsm;                 // [208][72]
    __nv_bfloat16* loP = gsm + JT * GSTR;

    const int tid = threadIdx.x;
    const int l = tid & 31;
    const int w = tid >> 5;
    const int split = blockIdx.x;
    const int b = blockIdx.y;

    const float* bases[3] = {
        rgb + (size_t)b * 64 * NPIX,
        hsv + (size_t)b * 64 * NPIX,
        lab + (size_t)b * 64 * NPIX
    };

    // static rows 192..207: row 192 hi = 1.0, everything else 0 (first 64 px)
    for (int idx = tid; idx < 2 * 16 * 32; idx += 256) {
        const int pl = idx >> 9;
        const int r = (idx >> 5) & 15;
        const int q = idx & 31;
        uint32_t* p = (uint32_t*)((pl ? loP : hiP) + (192 + r) * GSTR);
        p[q] = (pl == 0 && r == 0) ? 0x3F803F80u : 0u;
    }

    // per-warp tile table: flat upper-tri list of (mt, nt), mt 16-row, nt 8-col
    // row mt has tiles nt in [2mt, 26): lengths 26-2mt, total 182.
    const int wstart = w * 23 - ((w > 6) ? (w - 6) : 0);
    const int cnt = (w < 6) ? 23 : 22;
    int tinfo[23];
    {
        int mt = 0, rem = wstart;
        while (mt < 13 && rem >= 26 - 2 * mt) { rem -= 26 - 2 * mt; mt++; }
        int nt = 2 * mt + rem;
        for (int t = 0; t < 23; t++) {
            tinfo[t] = (mt << 8) | nt;
            nt++;
            if (nt >= 26) { mt++; nt = 2 * mt; }
        }
    }

    float acc[23][4];
#pragma unroll
    for (int t = 0; t < 23; t++)
#pragma unroll
        for (int q = 0; q < 4; q++) acc[t][q] = 0.0f;

    for (int chunk = split; chunk < NPIX / 64; chunk += SPLITS) {
        const int n0 = chunk * 64;
        __syncthreads();
        // stage rows 0..191: fp32 -> hi/lo bf16
        for (int idx = tid; idx < 192 * 32; idx += 256) {
            const int j = idx >> 5;
            const int pq = idx & 31;
            const float2 v = *(const float2*)(bases[j >> 6] +
                                              (size_t)(j & 63) * NPIX + n0 + pq * 2);
            unsigned short h0, l0, h1, l1;
            split_bf16(v.x, h0, l0);
            split_bf16(v.y, h1, l1);
            ((uint32_t*)(hiP + j * GSTR))[pq] = (uint32_t)h0 | ((uint32_t)h1 << 16);
            ((uint32_t*)(loP + j * GSTR))[pq] = (uint32_t)l0 | ((uint32_t)l1 << 16);
        }
        __syncthreads();

#pragma unroll 1
        for (int ks = 0; ks < 4; ks++) {
            int prev = -1;
            uint32_t ah0 = 0, ah1 = 0, ah2 = 0, ah3 = 0;
            uint32_t al0 = 0, al1 = 0, al2 = 0, al3 = 0;
#pragma unroll
            for (int t = 0; t < 23; t++) {
                if (t < cnt) {
                    const int info = tinfo[t];
                    const int mt = info >> 8;
                    const int nt = info & 255;
                    if (mt != prev) {
                        prev = mt;
                        const int arow = mt * 16 + (l >> 2);
                        const uint32_t* ph = (const uint32_t*)(hiP + arow * GSTR + ks * 16);
                        const uint32_t* pl8 = ph + 8 * (GSTR / 2);
                        ah0 = ph[l & 3];  ah2 = ph[(l & 3) + 4];
                        ah1 = pl8[l & 3]; ah3 = pl8[(l & 3) + 4];
                        const uint32_t* qh = (const uint32_t*)(loP + arow * GSTR + ks * 16);
                        const uint32_t* ql8 = qh + 8 * (GSTR / 2);
                        al0 = qh[l & 3];  al2 = qh[(l & 3) + 4];
                        al1 = ql8[l & 3]; al3 = ql8[(l & 3) + 4];
                    }
                    const int brow = nt * 8 + (l >> 2);
                    const uint32_t* pb = (const uint32_t*)(hiP + brow * GSTR + ks * 16);
                    const uint32_t bh0 = pb[l & 3], bh1 = pb[(l & 3) + 4];
                    const uint32_t* pbl = (const uint32_t*)(loP + brow * GSTR + ks * 16);
                    const uint32_t bl0 = pbl[l & 3], bl1 = pbl[(l & 3) + 4];
                    MMA16816(acc[t], ah0, ah1, ah2, ah3, bh0, bh1);  // hi*hi
                    MMA16816(acc[t], ah0, ah1, ah2, ah3, bl0, bl1);  // hi*lo
                    MMA16816(acc[t], al0, al1, al2, al3, bh0, bh1);  // lo*hi
                }
            }
        }
    }

    // epilogue: write tiles to split-K scratch
    float* gp = g_Gp + (size_t)(b * SPLITS + split) * JT * JT;
#pragma unroll
    for (int t = 0; t < 23; t++) {
        if (t < cnt) {
            const int info = tinfo[t];
            const int mt = info >> 8;
            const int nt = info & 255;
            const int i0 = mt * 16 + (l >> 2);
            const int j0 = nt * 8 + 2 * (l & 3);
            *(float2*)&gp[(size_t)i0 * JT + j0] = make_float2(acc[t][0], acc[t][1]);
            *(float2*)&gp[(size_t)(i0 + 8) * JT + j0] = make_float2(acc[t][2], acc[t][3]);
        }
    }
}

// ---------------------------------------------------------------------------
// kernel 2: reduce split-K + mirror lower triangle
// ---------------------------------------------------------------------------
__global__ void cam_reduceG() {
    const int idx = blockIdx.x * 256 + threadIdx.x;   // 4*208*208 exact
    const int b = idx / (JT * JT);
    const int rc = idx % (JT * JT);
    const int i = rc / JT, j = rc % JT;
    if (i > j) return;
    const float* gp = g_Gp + (size_t)b * SPLITS * JT * JT + rc;
    float acc = 0.0f;
#pragma unroll 4
    for (int s = 0; s < SPLITS; s++) acc += gp[(size_t)s * JT * JT];
    float* G = g_G + (size_t)b * JT * JT;
    G[i * JT + j] = acc;
    G[j * JT + i] = acc;
}

// ---------------------------------------------------------------------------
// kernel 3: T2[b][i][d] = sum_j G[b][i][j] Wk_aug[d][j]
// ---------------------------------------------------------------------------
__global__ void cam_projT2(const float* __restrict__ Wk,
                           const float* __restrict__ bk) {
    __shared__ float Gs[4][200];
    const int b = blockIdx.y;
    const int i0 = blockIdx.x * 4;
    const int tid = threadIdx.x;

    for (int idx = tid; idx < 4 * 193; idx += 256) {
        const int ii = idx / 193, j = idx % 193;
        if (i0 + ii < 193)
            Gs[ii][j] = g_G[(size_t)b * JT * JT + (size_t)(i0 + ii) * JT + j];
    }
    __syncthreads();

    const int d = tid & 63;
    const int ii = tid >> 6;
    const int i = i0 + ii;
    if (i < 193) {
        float acc = 0.0f;
#pragma unroll 4
        for (int j = 0; j < 192; j++) acc += Wk[d * 192 + j] * Gs[ii][j];
        acc += bk[d] * Gs[ii][192];
        g_T2[(size_t)b * 193 * 64 + i * 64 + d] = acc;
    }
}

// ---------------------------------------------------------------------------
// kernel 4: energy -> softmax -> M (bf16 hi/lo), one CTA per batch
// ---------------------------------------------------------------------------
#define ATTN_SMEM ((193 * 64 + 64 * 65) * 4)
__global__ void cam_attn2(const float* __restrict__ Wq,
                          const float* __restrict__ bq,
                          const float* __restrict__ Wv,
                          const float* __restrict__ bv) {
    extern __shared__ float asmf[];
    float* T2s = asmf;             // [193][64]
    float* Es = asmf + 193 * 64;   // [64][65]
    const int b = blockIdx.x;
    const int tid = threadIdx.x;

    for (int idx = tid; idx < 193 * 64; idx += 512)
        T2s[idx] = g_T2[(size_t)b * 193 * 64 + idx];
    __syncthreads();

    {
        const int c = tid >> 3;
        const int d0 = (tid & 7) * 8;
        float acc[8];
#pragma unroll
        for (int k = 0; k < 8; k++) acc[k] = 0.0f;
        for (int i = 0; i < 192; i++) {
            const float wv = Wq[c * 192 + i];
            const float* t = T2s + i * 64 + d0;
#pragma unroll
            for (int k = 0; k < 8; k++) acc[k] += wv * t[k];
        }
        {
            const float wv = bq[c];
            const float* t = T2s + 192 * 64 + d0;
#pragma unroll
            for (int k = 0; k < 8; k++) acc[k] += wv * t[k];
        }
#pragma unroll
        for (int k = 0; k < 8; k++) Es[c * 65 + d0 + k] = acc[k] * 0.125f;
    }
    __syncthreads();

    if (tid < 64) {
        float* row = Es + tid * 65;
        float mx = -1e30f;
#pragma unroll 4
        for (int k = 0; k < 64; k++) mx = fmaxf(mx, row[k]);
        float s = 0.0f;
#pragma unroll 4
        for (int k = 0; k < 64; k++) { row[k] = expf(row[k] - mx); s += row[k]; }
        const float inv = 1.0f / s;
#pragma unroll 4
        for (int k = 0; k < 64; k++) row[k] *= inv;
    }
    __syncthreads();

    for (int ent = tid; ent < 64 * JT; ent += 512) {
        const int c = ent / JT, j = ent % JT;
        const float* a = Es + c * 65;
        float m = 0.0f;
        if (j < 192) {
#pragma unroll 4
            for (int d = 0; d < 64; d++) m += a[d] * Wv[d * 192 + j];
        } else if (j == 192) {
#pragma unroll 4
            for (int d = 0; d < 64; d++) m += a[d] * bv[d];
        }
        unsigned short h, lo;
        split_bf16(m, h, lo);
        g_Mhi[(size_t)(b * 64 + c) * JT + j] = h;
        g_Mlo[(size_t)(b * 64 + c) * JT + j] = lo;
    }
}

// ---------------------------------------------------------------------------
// kernel 5: out[b] = M X_aug via mma.sync (A = M hi/lo, B = X via ldmatrix.trans)
// grid (256, 4), 256 threads; CTA tile: 64 ch x 256 px
// ---------------------------------------------------------------------------
#define OUT_SMEM (2 * 64 * ASTR * 2 + 2 * 64 * XSTR3 * 2)

__global__ __launch_bounds__(256, 1)
void cam_out_mma(const float* __restrict__ rgb,
                 const float* __restrict__ hsv,
                 const float* __restrict__ lab,
                 float* __restrict__ out) {
    extern __shared__ __align__(16) __nv_bfloat16 osm[];
    __nv_bfloat16* Ahi = osm;                        // [64][216]
    __nv_bfloat16* Alo = Ahi + 64 * ASTR;
    __nv_bfloat16* Xhi = Alo + 64 * ASTR;            // [64][264]
    __nv_bfloat16* Xlo = Xhi + 64 * XSTR3;

    const int tid = threadIdx.x;
    const int l = tid & 31;
    const int w = tid >> 5;
    const int wm = w >> 2;        // 0..1 (m-group of 32 ch)
    const int wn = w & 3;         // 0..3 (n-group of 64 px)
    const int b = blockIdx.y;
    const int px0 = blockIdx.x * 256;

    const float* bases[3] = {
        rgb + (size_t)b * 64 * NPIX,
        hsv + (size_t)b * 64 * NPIX,
        lab + (size_t)b * 64 * NPIX
    };

    // stage A = M hi/lo (64 x 208)
    const uint32_t* mhi = (const uint32_t*)(g_Mhi + (size_t)b * 64 * JT);
    const uint32_t* mlo = (const uint32_t*)(g_Mlo + (size_t)b * 64 * JT);
    for (int idx = tid; idx < 64 * 104; idx += 256) {
        const int c = idx / 104, kk = idx % 104;
        ((uint32_t*)(Ahi + c * ASTR))[kk] = mhi[c * 104 + kk];
        ((uint32_t*)(Alo + c * ASTR))[kk] = mlo[c * 104 + kk];
    }

    float acc[2][8][4];
#pragma unroll
    for (int mi = 0; mi < 2; mi++)
#pragma unroll
        for (int nt = 0; nt < 8; nt++)
#pragma unroll
            for (int q = 0; q < 4; q++) acc[mi][nt][q] = 0.0f;

    const uint32_t xhiA = smem_u32(Xhi);
    const uint32_t xloA = smem_u32(Xlo);

    for (int kc = 0; kc < JT; kc += 64) {
        const int klen = (kc + 64 <= JT) ? 64 : (JT - kc);
        __syncthreads();
        // stage X rows [kc, kc+klen) for this px tile
        for (int idx = tid; idx < klen * 128; idx += 256) {
            const int kr = idx >> 7;
            const int pq = idx & 127;
            const int ch = kc + kr;
            float2 v;
            if (ch < 192)
                v = *(const float2*)(bases[ch >> 6] + (size_t)(ch & 63) * NPIX +
                                     px0 + pq * 2);
            else if (ch == 192)
                v = make_float2(1.0f, 1.0f);
            else
                v = make_float2(0.0f, 0.0f);
            unsigned short h0, l0, h1, l1;
            split_bf16(v.x, h0, l0);
            split_bf16(v.y, h1, l1);
            ((uint32_t*)(Xhi + kr * XSTR3))[pq] = (uint32_t)h0 | ((uint32_t)h1 << 16);
            ((uint32_t*)(Xlo + kr * XSTR3))[pq] = (uint32_t)l0 | ((uint32_t)l1 << 16);
        }
        __syncthreads();

        const int nks = klen / 16;
#pragma unroll 1
        for (int ks = 0; ks < nks; ks++) {
            // A fragments for this warp's two m-tiles, both planes
            uint32_t AH[2][4], AL[2][4];
#pragma unroll
            for (int mi = 0; mi < 2; mi++) {
                const int arow = (wm * 2 + mi) * 16 + (l >> 2);
                const uint32_t* ph = (const uint32_t*)(Ahi + arow * ASTR + kc + ks * 16);
                const uint32_t* ph8 = ph + 8 * (ASTR / 2);
                AH[mi][0] = ph[l & 3];  AH[mi][2] = ph[(l & 3) + 4];
                AH[mi][1] = ph8[l & 3]; AH[mi][3] = ph8[(l & 3) + 4];
                const uint32_t* ql = (const uint32_t*)(Alo + arow * ASTR + kc + ks * 16);
                const uint32_t* ql8 = ql + 8 * (ASTR / 2);
                AL[mi][0] = ql[l & 3];  AL[mi][2] = ql[(l & 3) + 4];
                AL[mi][1] = ql8[l & 3]; AL[mi][3] = ql8[(l & 3) + 4];
            }
            const uint32_t rowoff = (uint32_t)(ks * 16 + (l & 15)) * (XSTR3 * 2);
#pragma unroll
            for (int nt = 0; nt < 8; nt++) {
                const uint32_t coloff = (uint32_t)(wn * 64 + nt * 8) * 2;
                uint32_t bh0, bh1, bl0, bl1;
                LDSM_X2_T(bh0, bh1, xhiA + rowoff + coloff);
                LDSM_X2_T(bl0, bl1, xloA + rowoff + coloff);
#pragma unroll
                for (int mi = 0; mi < 2; mi++) {
                    MMA16816(acc[mi][nt], AH[mi][0], AH[mi][1], AH[mi][2], AH[mi][3], bh0, bh1);
                    MMA16816(acc[mi][nt], AH[mi][0], AH[mi][1], AH[mi][2], AH[mi][3], bl0, bl1);
                    MMA16816(acc[mi][nt], AL[mi][0], AL[mi][1], AL[mi][2], AL[mi][3], bh0, bh1);
                }
            }
        }
    }

    // epilogue: direct float2 stores
#pragma unroll
    for (int mi = 0; mi < 2; mi++) {
        const int c0 = (wm * 2 + mi) * 16 + (l >> 2);
#pragma unroll
        for (int nt = 0; nt < 8; nt++) {
            const int px = px0 + wn * 64 + nt * 8 + 2 * (l & 3);
            float* op = out + (size_t)(b * 64 + c0) * NPIX + px;
            *(float2*)op = make_float2(acc[mi][nt][0], acc[mi][nt][1]);
            *(float2*)(op + 8 * NPIX) = make_float2(acc[mi][nt][2], acc[mi][nt][3]);
        }
    }
}

// ---------------------------------------------------------------------------
// launch
// ---------------------------------------------------------------------------
extern "C" void kernel_launch(void* const* d_in, const int* in_sizes, int n_in,
                              void* d_out, int out_size) {
    const float* rgb = (const float*)d_in[0];
    const float* hsv = (const float*)d_in[1];
    const float* lab = (const float*)d_in[2];
    const float* Wq  = (const float*)d_in[3];
    const float* bq  = (const float*)d_in[4];
    const float* Wk  = (const float*)d_in[5];
    const float* bk  = (const float*)d_in[6];
    const float* Wv  = (const float*)d_in[7];
    const float* bv  = (const float*)d_in[8];
    float* out = (float*)d_out;

    cudaFuncSetAttribute(cam_gram_mma, cudaFuncAttributeMaxDynamicSharedMemorySize, GRAM_SMEM);
    cudaFuncSetAttribute(cam_attn2, cudaFuncAttributeMaxDynamicSharedMemorySize, ATTN_SMEM);
    cudaFuncSetAttribute(cam_out_mma, cudaFuncAttributeMaxDynamicSharedMemorySize, OUT_SMEM);

    cam_gram_mma<<<dim3(SPLITS, 4), 256, GRAM_SMEM>>>(rgb, hsv, lab);
    cam_reduceG<<<(4 * JT * JT) / 256, 256>>>();
    cam_projT2<<<dim3(49, 4), 256>>>(Wk, bk);
    cam_attn2<<<4, 512, ATTN_SMEM>>>(Wq, bq, Wv, bv);
    cam_out_mma<<<dim3(NPIX / 256, 4), 256, OUT_SMEM>>>(rgb, hsv, lab, out);
}

// round 6
// speedup vs baseline: 2.0862x; 1.8351x over previous
#include <cuda_runtime.h>
#include <cuda_bf16.h>
#include <cstdint>

// ============================================================================
// CAM via Gram restructuring, mma.sync bf16 hi/lo (sm_100-safe PTX).
//   Gram: 512-thread CTAs, 16 warps x ~11 upper-tri (16x8) tiles, 128-px chunks
//   out : 64ch x 128px CTA tile, 2 CTAs/SM
//   attn chain: wide coalesced kernels
// ============================================================================

#define NPIX   65536
#define JT     208
#define SPLITS 37
#define GCH    128    // gram pixels per chunk
#define GSTR   136    // gram smem row stride (bf16)
#define ASTR   216    // out A smem stride (bf16)
#define OXS    136    // out X smem stride (bf16)
#define OTN    128    // out pixels per CTA

__device__ float g_Gp[4 * SPLITS * JT * JT];
__device__ float g_G[4 * JT * JT];
__device__ float g_T2[4 * 193 * 64];
__device__ float g_A[4 * 64 * 64];
__device__ unsigned short g_Mhi[4 * 64 * JT];
__device__ unsigned short g_Mlo[4 * 64 * JT];

// ---------------------------------------------------------------------------
static __device__ __forceinline__ uint32_t smem_u32(const void* p) {
    uint32_t a;
    asm("{ .reg .u64 t; cvta.to.shared.u64 t, %1; cvt.u32.u64 %0, t; }"
        : "=r"(a) : "l"(p));
    return a;
}

#define MMA16816(d, a0, a1, a2, a3, b0, b1) \
    asm volatile("mma.sync.aligned.m16n8k16.row.col.f32.bf16.bf16.f32 " \
        "{%0,%1,%2,%3}, {%4,%5,%6,%7}, {%8,%9}, {%0,%1,%2,%3};" \
        : "+f"((d)[0]), "+f"((d)[1]), "+f"((d)[2]), "+f"((d)[3]) \
        : "r"(a0), "r"(a1), "r"(a2), "r"(a3), "r"(b0), "r"(b1))

#define LDSM_X2_T(r0, r1, addr) \
    asm volatile("ldmatrix.sync.aligned.m8n8.x2.trans.shared.b16 {%0,%1}, [%2];" \
        : "=r"(r0), "=r"(r1) : "r"(addr))

static __device__ __forceinline__ void split_bf16(float x, unsigned short& h,
                                                  unsigned short& lo) {
    __nv_bfloat16 hb = __float2bfloat16(x);
    __nv_bfloat16 lb = __float2bfloat16(x - __bfloat162float(hb));
    h = __bfloat16_as_ushort(hb);
    lo = __bfloat16_as_ushort(lb);
}

// ---------------------------------------------------------------------------
// kernel 1: split-K Gram (upper triangle), 512 threads, 128-px chunks
// ---------------------------------------------------------------------------
#define GRAM_SMEM (2 * JT * GSTR * 2)

__global__ __launch_bounds__(512, 1)
void cam_gram_mma(const float* __restrict__ rgb,
                  const float* __restrict__ hsv,
                  const float* __restrict__ lab) {
    extern __shared__ __align__(16) __nv_bfloat16 gsm[];
    __nv_bfloat16* hiP = gsm;                 // [208][136]
    __nv_bfloat16* loP = gsm + JT * GSTR;

    const int tid = threadIdx.x;
    const int l = tid & 31;
    const int w = tid >> 5;       // 0..15
    const int split = blockIdx.x;
    const int b = blockIdx.y;

    const float* bases[3] = {
        rgb + (size_t)b * 64 * NPIX,
        hsv + (size_t)b * 64 * NPIX,
        lab + (size_t)b * 64 * NPIX
    };

    // static rows 192..207 (row 192 hi = 1.0, else 0) across the 128-px width
    for (int idx = tid; idx < 2 * 16 * 64; idx += 512) {
        const int pl = idx >> 10;
        const int r = (idx >> 6) & 15;
        const int q = idx & 63;
        uint32_t* p = (uint32_t*)((pl ? loP : hiP) + (192 + r) * GSTR);
        p[q] = (pl == 0 && r == 0) ? 0x3F803F80u : 0u;
    }

    // per-warp contiguous tile range over 182 upper-tri tiles
    const int start = (w < 6) ? 12 * w : (11 * w + 6);
    const int cnt = (w < 6) ? 12 : 11;
    int mtA[12], ntA[12];
    {
        int rem = start, mt = 0;
        while (mt < 13 && rem >= 26 - 2 * mt) { rem -= 26 - 2 * mt; mt++; }
        int nt = 2 * mt + rem;
#pragma unroll
        for (int t = 0; t < 12; t++) {
            if (mt >= 13) { mt = 12; nt = 25; }   // padding (never stored)
            mtA[t] = mt; ntA[t] = nt;
            nt++;
            if (nt >= 26) { mt++; nt = 2 * mt; }
        }
    }

    float acc[12][4];
#pragma unroll
    for (int t = 0; t < 12; t++)
#pragma unroll
        for (int q = 0; q < 4; q++) acc[t][q] = 0.0f;

    for (int chunk = split; chunk < NPIX / GCH; chunk += SPLITS) {
        const int n0 = chunk * GCH;
        __syncthreads();
        // stage rows 0..191: fp32 -> hi/lo bf16 (128 px)
        for (int idx = tid; idx < 192 * 64; idx += 512) {
            const int j = idx >> 6;
            const int pq = idx & 63;
            const float2 v = *(const float2*)(bases[j >> 6] +
                                              (size_t)(j & 63) * NPIX + n0 + pq * 2);
            unsigned short h0, l0, h1, l1;
            split_bf16(v.x, h0, l0);
            split_bf16(v.y, h1, l1);
            ((uint32_t*)(hiP + j * GSTR))[pq] = (uint32_t)h0 | ((uint32_t)h1 << 16);
            ((uint32_t*)(loP + j * GSTR))[pq] = (uint32_t)l0 | ((uint32_t)l1 << 16);
        }
        __syncthreads();

#pragma unroll 1
        for (int ks = 0; ks < GCH / 16; ks++) {
            int prev = -1;
            uint32_t ah0 = 0, ah1 = 0, ah2 = 0, ah3 = 0;
            uint32_t al0 = 0, al1 = 0, al2 = 0, al3 = 0;
#pragma unroll
            for (int t = 0; t < 12; t++) {
                if (t < cnt) {
                    const int mt = mtA[t];
                    const int nt = ntA[t];
                    if (mt != prev) {
                        prev = mt;
                        const int arow = mt * 16 + (l >> 2);
                        const uint32_t* ph = (const uint32_t*)(hiP + arow * GSTR + ks * 16);
                        const uint32_t* ph8 = ph + 8 * (GSTR / 2);
                        ah0 = ph[l & 3];  ah2 = ph[(l & 3) + 4];
                        ah1 = ph8[l & 3]; ah3 = ph8[(l & 3) + 4];
                        const uint32_t* ql = (const uint32_t*)(loP + arow * GSTR + ks * 16);
                        const uint32_t* ql8 = ql + 8 * (GSTR / 2);
                        al0 = ql[l & 3];  al2 = ql[(l & 3) + 4];
                        al1 = ql8[l & 3]; al3 = ql8[(l & 3) + 4];
                    }
                    const int brow = nt * 8 + (l >> 2);
                    const uint32_t* pb = (const uint32_t*)(hiP + brow * GSTR + ks * 16);
                    const uint32_t bh0 = pb[l & 3], bh1 = pb[(l & 3) + 4];
                    const uint32_t* pbl = (const uint32_t*)(loP + brow * GSTR + ks * 16);
                    const uint32_t bl0 = pbl[l & 3], bl1 = pbl[(l & 3) + 4];
                    MMA16816(acc[t], ah0, ah1, ah2, ah3, bh0, bh1);
                    MMA16816(acc[t], ah0, ah1, ah2, ah3, bl0, bl1);
                    MMA16816(acc[t], al0, al1, al2, al3, bh0, bh1);
                }
            }
        }
    }

    float* gp = g_Gp + (size_t)(b * SPLITS + split) * JT * JT;
#pragma unroll
    for (int t = 0; t < 12; t++) {
        if (t < cnt) {
            const int i0 = mtA[t] * 16 + (l >> 2);
            const int j0 = ntA[t] * 8 + 2 * (l & 3);
            *(float2*)&gp[(size_t)i0 * JT + j0] = make_float2(acc[t][0], acc[t][1]);
            *(float2*)&gp[(size_t)(i0 + 8) * JT + j0] = make_float2(acc[t][2], acc[t][3]);
        }
    }
}

// ---------------------------------------------------------------------------
// kernel 2: reduce split-K + mirror
// ---------------------------------------------------------------------------
__global__ void cam_reduceG() {
    const int idx = blockIdx.x * 256 + threadIdx.x;   // 4*208*208 exact
    const int b = idx / (JT * JT);
    const int rc = idx % (JT * JT);
    const int i = rc / JT, j = rc % JT;
    if (i > j) return;
    const float* gp = g_Gp + (size_t)b * SPLITS * JT * JT + rc;
    float acc = 0.0f;
#pragma unroll 4
    for (int s = 0; s < SPLITS; s++) acc += gp[(size_t)s * JT * JT];
    float* G = g_G + (size_t)b * JT * JT;
    G[i * JT + j] = acc;
    G[j * JT + i] = acc;
}

// ---------------------------------------------------------------------------
// kernel 3: T2[b][i][d] = sum_j G[b][i][j] Wk_aug[d][j]
// ---------------------------------------------------------------------------
__global__ void cam_projT2(const float* __restrict__ Wk,
                           const float* __restrict__ bk) {
    __shared__ float Gs[4][200];
    const int b = blockIdx.y;
    const int i0 = blockIdx.x * 4;
    const int tid = threadIdx.x;

    for (int idx = tid; idx < 4 * 193; idx += 256) {
        const int ii = idx / 193, j = idx % 193;
        if (i0 + ii < 193)
            Gs[ii][j] = g_G[(size_t)b * JT * JT + (size_t)(i0 + ii) * JT + j];
    }
    __syncthreads();

    const int d = tid & 63;
    const int ii = tid >> 6;
    const int i = i0 + ii;
    if (i < 193) {
        float acc = 0.0f;
#pragma unroll 4
        for (int j = 0; j < 192; j++) acc += Wk[d * 192 + j] * Gs[ii][j];
        acc += bk[d] * Gs[ii][192];
        g_T2[(size_t)b * 193 * 64 + i * 64 + d] = acc;
    }
}

// ---------------------------------------------------------------------------
// kernel 4a: E[c][d] -> softmax row c -> A   (grid (64,4), 64 threads)
// ---------------------------------------------------------------------------
__global__ void cam_energy(const float* __restrict__ Wq,
                           const float* __restrict__ bq) {
    __shared__ float se[64];
    const int c = blockIdx.x;
    const int b = blockIdx.y;
    const int d = threadIdx.x;

    const float* T2b = g_T2 + (size_t)b * 193 * 64;
    float e = 0.0f;
#pragma unroll 4
    for (int i = 0; i < 192; i++) e += Wq[c * 192 + i] * T2b[i * 64 + d];
    e += bq[c] * T2b[192 * 64 + d];
    e *= 0.125f;
    se[d] = e;
    __syncthreads();

    float mx = -1e30f;
#pragma unroll 4
    for (int k = 0; k < 64; k++) mx = fmaxf(mx, se[k]);
    float s = 0.0f;
#pragma unroll 4
    for (int k = 0; k < 64; k++) s += expf(se[k] - mx);
    g_A[((size_t)b * 64 + c) * 64 + d] = expf(e - mx) / s;
}

// ---------------------------------------------------------------------------
// kernel 4b: M[c][j] = sum_d A[c][d] Wv_aug[d][j]  (grid (64,4), 256 threads)
// ---------------------------------------------------------------------------
__global__ void cam_M(const float* __restrict__ Wv,
                      const float* __restrict__ bv) {
    __shared__ float As[64];
    const int c = blockIdx.x;
    const int b = blockIdx.y;
    const int tid = threadIdx.x;

    if (tid < 64) As[tid] = g_A[((size_t)b * 64 + c) * 64 + tid];
    __syncthreads();

    const int j = tid;
    if (j < JT) {
        float m = 0.0f;
        if (j < 192) {
#pragma unroll 4
            for (int d = 0; d < 64; d++) m += As[d] * Wv[d * 192 + j];
        } else if (j == 192) {
#pragma unroll 4
            for (int d = 0; d < 64; d++) m += As[d] * bv[d];
        }
        unsigned short h, lo;
        split_bf16(m, h, lo);
        g_Mhi[(size_t)(b * 64 + c) * JT + j] = h;
        g_Mlo[(size_t)(b * 64 + c) * JT + j] = lo;
    }
}

// ---------------------------------------------------------------------------
// kernel 5: out[b] = M X_aug  (64ch x 128px CTA tile, 2 CTAs/SM)
// ---------------------------------------------------------------------------
#define OUT_SMEM (2 * 64 * ASTR * 2 + 2 * 64 * OXS * 2)

__global__ __launch_bounds__(256, 2)
void cam_out_mma(const float* __restrict__ rgb,
                 const float* __restrict__ hsv,
                 const float* __restrict__ lab,
                 float* __restrict__ out) {
    extern __shared__ __align__(16) __nv_bfloat16 osm[];
    __nv_bfloat16* Ahi = osm;                        // [64][216]
    __nv_bfloat16* Alo = Ahi + 64 * ASTR;
    __nv_bfloat16* Xhi = Alo + 64 * ASTR;            // [64][136]
    __nv_bfloat16* Xlo = Xhi + 64 * OXS;

    const int tid = threadIdx.x;
    const int l = tid & 31;
    const int w = tid >> 5;
    const int wm = w >> 2;        // 0..1 (32-ch group)
    const int wn = w & 3;         // 0..3 (32-px group)
    const int b = blockIdx.y;
    const int px0 = blockIdx.x * OTN;

    const float* bases[3] = {
        rgb + (size_t)b * 64 * NPIX,
        hsv + (size_t)b * 64 * NPIX,
        lab + (size_t)b * 64 * NPIX
    };

    // stage A = M hi/lo (64 x 208)
    const uint32_t* mhi = (const uint32_t*)(g_Mhi + (size_t)b * 64 * JT);
    const uint32_t* mlo = (const uint32_t*)(g_Mlo + (size_t)b * 64 * JT);
    for (int idx = tid; idx < 64 * 104; idx += 256) {
        const int c = idx / 104, kk = idx % 104;
        ((uint32_t*)(Ahi + c * ASTR))[kk] = mhi[c * 104 + kk];
        ((uint32_t*)(Alo + c * ASTR))[kk] = mlo[c * 104 + kk];
    }

    float acc[2][4][4];
#pragma unroll
    for (int mi = 0; mi < 2; mi++)
#pragma unroll
        for (int nt = 0; nt < 4; nt++)
#pragma unroll
            for (int q = 0; q < 4; q++) acc[mi][nt][q] = 0.0f;

    const uint32_t xhiA = smem_u32(Xhi);
    const uint32_t xloA = smem_u32(Xlo);

    for (int kc = 0; kc < JT; kc += 64) {
        const int klen = (kc + 64 <= JT) ? 64 : (JT - kc);
        __syncthreads();
        // stage X rows [kc, kc+klen), 128 px
        for (int idx = tid; idx < klen * 64; idx += 256) {
            const int kr = idx >> 6;
            const int pq = idx & 63;
            const int ch = kc + kr;
            float2 v;
            if (ch < 192)
                v = *(const float2*)(bases[ch >> 6] + (size_t)(ch & 63) * NPIX +
                                     px0 + pq * 2);
            else if (ch == 192)
                v = make_float2(1.0f, 1.0f);
            else
                v = make_float2(0.0f, 0.0f);
            unsigned short h0, l0, h1, l1;
            split_bf16(v.x, h0, l0);
            split_bf16(v.y, h1, l1);
            ((uint32_t*)(Xhi + kr * OXS))[pq] = (uint32_t)h0 | ((uint32_t)h1 << 16);
            ((uint32_t*)(Xlo + kr * OXS))[pq] = (uint32_t)l0 | ((uint32_t)l1 << 16);
        }
        __syncthreads();

        const int nks = klen / 16;
#pragma unroll 1
        for (int ks = 0; ks < nks; ks++) {
            uint32_t AH[2][4], AL[2][4];
#pragma unroll
            for (int mi = 0; mi < 2; mi++) {
                const int arow = (wm * 2 + mi) * 16 + (l >> 2);
                const uint32_t* ph = (const uint32_t*)(Ahi + arow * ASTR + kc + ks * 16);
                const uint32_t* ph8 = ph + 8 * (ASTR / 2);
                AH[mi][0] = ph[l & 3];  AH[mi][2] = ph[(l & 3) + 4];
                AH[mi][1] = ph8[l & 3]; AH[mi][3] = ph8[(l & 3) + 4];
                const uint32_t* ql = (const uint32_t*)(Alo + arow * ASTR + kc + ks * 16);
                const uint32_t* ql8 = ql + 8 * (ASTR / 2);
                AL[mi][0] = ql[l & 3];  AL[mi][2] = ql[(l & 3) + 4];
                AL[mi][1] = ql8[l & 3]; AL[mi][3] = ql8[(l & 3) + 4];
            }
            const uint32_t rowoff = (uint32_t)(ks * 16 + (l & 15)) * (OXS * 2);
#pragma unroll
            for (int nt = 0; nt < 4; nt++) {
                const uint32_t coloff = (uint32_t)(wn * 32 + nt * 8) * 2;
                uint32_t bh0, bh1, bl0, bl1;
                LDSM_X2_T(bh0, bh1, xhiA + rowoff + coloff);
                LDSM_X2_T(bl0, bl1, xloA + rowoff + coloff);
#pragma unroll
                for (int mi = 0; mi < 2; mi++) {
                    MMA16816(acc[mi][nt], AH[mi][0], AH[mi][1], AH[mi][2], AH[mi][3], bh0, bh1);
                    MMA16816(acc[mi][nt], AH[mi][0], AH[mi][1], AH[mi][2], AH[mi][3], bl0, bl1);
                    MMA16816(acc[mi][nt], AL[mi][0], AL[mi][1], AL[mi][2], AL[mi][3], bh0, bh1);
                }
            }
        }
    }

#pragma unroll
    for (int mi = 0; mi < 2; mi++) {
        const int c0 = (wm * 2 + mi) * 16 + (l >> 2);
#pragma unroll
        for (int nt = 0; nt < 4; nt++) {
            const int px = px0 + wn * 32 + nt * 8 + 2 * (l & 3);
            float* op = out + (size_t)(b * 64 + c0) * NPIX + px;
            *(float2*)op = make_float2(acc[mi][nt][0], acc[mi][nt][1]);
            *(float2*)(op + 8 * NPIX) = make_float2(acc[mi][nt][2], acc[mi][nt][3]);
        }
    }
}

// ---------------------------------------------------------------------------
// launch
// ---------------------------------------------------------------------------
extern "C" void kernel_launch(void* const* d_in, const int* in_sizes, int n_in,
                              void* d_out, int out_size) {
    const float* rgb = (const float*)d_in[0];
    const float* hsv = (const float*)d_in[1];
    const float* lab = (const float*)d_in[2];
    const float* Wq  = (const float*)d_in[3];
    const float* bq  = (const float*)d_in[4];
    const float* Wk  = (const float*)d_in[5];
    const float* bk  = (const float*)d_in[6];
    const float* Wv  = (const float*)d_in[7];
    const float* bv  = (const float*)d_in[8];
    float* out = (float*)d_out;

    cudaFuncSetAttribute(cam_gram_mma, cudaFuncAttributeMaxDynamicSharedMemorySize, GRAM_SMEM);
    cudaFuncSetAttribute(cam_out_mma, cudaFuncAttributeMaxDynamicSharedMemorySize, OUT_SMEM);

    cam_gram_mma<<<dim3(SPLITS, 4), 512, GRAM_SMEM>>>(rgb, hsv, lab);
    cam_reduceG<<<(4 * JT * JT) / 256, 256>>>();
    cam_projT2<<<dim3(49, 4), 256>>>(Wk, bk);
    cam_energy<<<dim3(64, 4), 64>>>(Wq, bq);
    cam_M<<<dim3(64, 4), 256>>>(Wv, bv);
    cam_out_mma<<<dim3(NPIX / OTN, 4), 256, OUT_SMEM>>>(rgb, hsv, lab, out);
}